// round 13
// baseline (speedup 1.0000x reference)
#include <cuda_runtime.h>
#include <cuda_fp16.h>
#include <math.h>
#include <cstdint>
#include <cstddef>

#define BQ 2048
#define NT 49
#define CD 384
#define NH 12
#define HD 32
#define MROWS (BQ*NT)        // 100352
#define QKVN (3*CD)          // 1152
#define RPE 512
#define TBL 169
#define LOG_MAX_SCALE 4.60517018598809136804f

__device__ float g_qkv[(size_t)MROWS * QKVN];
__device__ float g_ao[(size_t)MROWS * CD];
__device__ float g_tab[TBL * NH];
__device__ float g_bias[NH * NT * NT];

// ---------------------------------------------------------------------------
__global__ void cpb_mlp_kernel(const float* __restrict__ w1,
                               const float* __restrict__ b1,
                               const float* __restrict__ w2)
{
    int i2 = blockIdx.x;
    int a = i2 / 13, bcol = i2 % 13;
    float vy = (float)(a - 6) * (8.0f / 6.0f);
    float vx = (float)(bcol - 6) * (8.0f / 6.0f);
    float t0 = copysignf(log2f(fabsf(vy) + 1.0f) / 3.0f, vy);
    float t1 = copysignf(log2f(fabsf(vx) + 1.0f) / 3.0f, vx);

    __shared__ float hidden[RPE];
    __shared__ float red[4];
    int tid = threadIdx.x;
    for (int r = tid; r < RPE; r += 128) {
        float hv = t0 * w1[2 * r] + t1 * w1[2 * r + 1] + b1[r];
        hidden[r] = fmaxf(hv, 0.0f);
    }
    __syncthreads();
    for (int h = 0; h < NH; h++) {
        float p = 0.0f;
        for (int r = tid; r < RPE; r += 128) p += hidden[r] * w2[h * RPE + r];
        #pragma unroll
        for (int o = 16; o > 0; o >>= 1) p += __shfl_xor_sync(0xffffffffu, p, o);
        if ((tid & 31) == 0) red[tid >> 5] = p;
        __syncthreads();
        if (tid == 0) g_tab[i2 * NH + h] = red[0] + red[1] + red[2] + red[3];
        __syncthreads();
    }
}

__global__ void bias_expand_kernel()
{
    int t = blockIdx.x * 256 + threadIdx.x;
    if (t >= NH * NT * NT) return;
    int h = t / (NT * NT);
    int ij = t % (NT * NT);
    int i = ij / NT, j = ij % NT;
    int rel = ((i / 7 - j / 7) + 6) * 13 + ((i % 7 - j % 7) + 6);
    float x = g_tab[rel * NH + h];
    g_bias[t] = 16.0f / (1.0f + __expf(-x));
}

// ---------------------------------------------------------------------------
// common MMA helpers
// ---------------------------------------------------------------------------
__device__ __forceinline__ uint32_t smem_u32(const void* p) {
    uint32_t a;
    asm("{ .reg .u64 t; cvta.to.shared.u64 t, %1; cvt.u32.u64 %0, t; }"
        : "=r"(a) : "l"(p));
    return a;
}

__device__ __forceinline__ uint2 pack4h(float4 v) {
    __half2 h0 = __floats2half2_rn(v.x, v.y);
    __half2 h1 = __floats2half2_rn(v.z, v.w);
    uint2 r;
    r.x = *(uint32_t*)&h0;
    r.y = *(uint32_t*)&h1;
    return r;
}

#define LDSM4(r0, r1, r2, r3, a) \
    asm volatile("ldmatrix.sync.aligned.m8n8.x4.shared.b16 {%0,%1,%2,%3}, [%4];" \
                 : "=r"(r0), "=r"(r1), "=r"(r2), "=r"(r3) : "r"(a))

__device__ __forceinline__ void mma_fp16(float c[4], uint32_t a0, uint32_t a1,
                                         uint32_t a2, uint32_t a3,
                                         uint32_t b0, uint32_t b1) {
    asm volatile(
        "mma.sync.aligned.m16n8k16.row.col.f32.f16.f16.f32 "
        "{%0,%1,%2,%3}, {%4,%5,%6,%7}, {%8,%9}, {%0,%1,%2,%3};"
        : "+f"(c[0]), "+f"(c[1]), "+f"(c[2]), "+f"(c[3])
        : "r"(a0), "r"(a1), "r"(a2), "r"(a3), "r"(b0), "r"(b1));
}

__device__ __forceinline__ void pack_hl(float f0, float f1, uint32_t& hi, uint32_t& lo) {
    __half h0 = __float2half_rn(f0), h1 = __float2half_rn(f1);
    __half l0 = __float2half_rn(f0 - __half2float(h0));
    __half l1 = __float2half_rn(f1 - __half2float(h1));
    hi = (uint32_t)(*(uint16_t*)&h0) | ((uint32_t)(*(uint16_t*)&h1) << 16);
    lo = (uint32_t)(*(uint16_t*)&l0) | ((uint32_t)(*(uint16_t*)&l1) << 16);
}

__device__ __forceinline__ void split_store(uint16_t* hi_p, uint16_t* lo_p, float f) {
    __half h = __float2half_rn(f);
    __half l = __float2half_rn(f - __half2float(h));
    *hi_p = *(uint16_t*)&h;
    *lo_p = *(uint16_t*)&l;
}

// ---------------------------------------------------------------------------
// FP16 tensor-core GEMM (double-buffered) — unchanged
// ---------------------------------------------------------------------------
#define HROW 40
#define BUFB (128 * HROW * 2)

template<int NC, int MODE>
__global__ void __launch_bounds__(256, 2) gemm_fp16(
    const float* __restrict__ A, const float* __restrict__ B,
    float* __restrict__ C,
    const float* __restrict__ bias0, const float* __restrict__ bias1)
{
    constexpr int K = 384;
    __shared__ __align__(16) uint16_t As[2][128 * HROW];
    __shared__ __align__(16) uint16_t Bs[2][128 * HROW];

    int tid = threadIdx.x;
    int lane = tid & 31, w = tid >> 5;
    int g = lane >> 2, t4 = lane & 3;
    int warp_m = (w >> 1) * 32;
    int warp_n = (w & 1) * 64;
    int m0 = blockIdx.y * 128;
    int n0 = blockIdx.x * 128;

    uint32_t as_u = smem_u32(As), bs_u = smem_u32(Bs);
    int arow = warp_m + ((lane >> 3) & 1) * 8 + (lane & 7);
    uint32_t aaddr = as_u + arow * 80 + (lane >> 4) * 16;
    int brow = warp_n + ((lane >> 4) & 1) * 8 + (lane & 7);
    uint32_t baddr = bs_u + brow * 80 + ((lane >> 3) & 1) * 16;

    int lr = tid >> 3;
    int lc = (tid & 7) * 4;

    const float* Ap = A + (size_t)(m0 + lr) * K + lc;
    const float* Bp = B + (size_t)(n0 + lr) * K + lc;

    float acc[2][8][4];
    #pragma unroll
    for (int mi = 0; mi < 2; mi++)
        #pragma unroll
        for (int ni = 0; ni < 8; ni++)
            #pragma unroll
            for (int q = 0; q < 4; q++) acc[mi][ni][q] = 0.0f;

    uint2 ra[4], rb[4];
    #pragma unroll
    for (int p = 0; p < 4; p++) {
        ra[p] = pack4h(*(const float4*)(Ap + (size_t)(32 * p) * K));
        rb[p] = pack4h(*(const float4*)(Bp + (size_t)(32 * p) * K));
    }
    #pragma unroll
    for (int p = 0; p < 4; p++) {
        int row = lr + 32 * p;
        *(uint2*)(As[0] + row * HROW + lc) = ra[p];
        *(uint2*)(Bs[0] + row * HROW + lc) = rb[p];
    }
    __syncthreads();

    int buf = 0;
    for (int k0 = 0; k0 < K; k0 += 32, buf ^= 1) {
        bool more = (k0 + 32 < K);
        if (more) {
            #pragma unroll
            for (int p = 0; p < 4; p++) {
                ra[p] = pack4h(*(const float4*)(Ap + (size_t)(32 * p) * K + (k0 + 32)));
                rb[p] = pack4h(*(const float4*)(Bp + (size_t)(32 * p) * K + (k0 + 32)));
            }
        }

        uint32_t ab = aaddr + buf * BUFB;
        uint32_t bb = baddr + buf * BUFB;
        #pragma unroll
        for (int kk = 0; kk < 2; kk++) {
            uint32_t kb = kk * 32;
            uint32_t af[2][4], bq[4][4];
            #pragma unroll
            for (int mi = 0; mi < 2; mi++)
                LDSM4(af[mi][0], af[mi][1], af[mi][2], af[mi][3],
                      ab + mi * 1280 + kb);
            #pragma unroll
            for (int p = 0; p < 4; p++)
                LDSM4(bq[p][0], bq[p][1], bq[p][2], bq[p][3],
                      bb + p * 1280 + kb);
            #pragma unroll
            for (int mi = 0; mi < 2; mi++)
                #pragma unroll
                for (int ni = 0; ni < 8; ni++) {
                    int p = ni >> 1, hsel = (ni & 1) * 2;
                    mma_fp16(acc[mi][ni], af[mi][0], af[mi][1], af[mi][2], af[mi][3],
                             bq[p][hsel], bq[p][hsel + 1]);
                }
        }

        if (more) {
            int nb = buf ^ 1;
            #pragma unroll
            for (int p = 0; p < 4; p++) {
                int row = lr + 32 * p;
                *(uint2*)(As[nb] + row * HROW + lc) = ra[p];
                *(uint2*)(Bs[nb] + row * HROW + lc) = rb[p];
            }
        }
        __syncthreads();
    }

    #pragma unroll
    for (int ni = 0; ni < 8; ni++) {
        int col = n0 + warp_n + ni * 8 + 2 * t4;
        float bx, by;
        if (MODE == 0) {
            bx = (col < CD) ? bias0[col] : ((col < 2 * CD) ? 0.0f : bias1[col - 2 * CD]);
            int c1 = col + 1;
            by = (c1 < CD) ? bias0[c1] : ((c1 < 2 * CD) ? 0.0f : bias1[c1 - 2 * CD]);
        } else {
            bx = bias0[col]; by = bias0[col + 1];
        }
        #pragma unroll
        for (int mi = 0; mi < 2; mi++) {
            int row = m0 + warp_m + mi * 16 + g;
            float2 o0 = make_float2(acc[mi][ni][0] + bx, acc[mi][ni][1] + by);
            float2 o1 = make_float2(acc[mi][ni][2] + bx, acc[mi][ni][3] + by);
            *(float2*)(C + (size_t)row * NC + col) = o0;
            *(float2*)(C + (size_t)(row + 8) * NC + col) = o1;
        }
    }
}

// ---------------------------------------------------------------------------
// MMA attention v2: V^T overlays the q smem buffer (loaded after QK phase),
// no blanket zeroing (only V tail), 64-reg / 8-CTA occupancy target.
// ---------------------------------------------------------------------------
#define AQ_STR 40                  // halves per q/k row (32 + 8 pad), 80 B
#define AV_STR 72                  // halves per v^T row (64 + 8 pad), 144 B
#define QK_BUF (64 * AQ_STR)       // 2560 halves per split buffer
#define QK_BUFB (QK_BUF * 2)       // 5120 bytes
#define VT_BUF (32 * AV_STR)       // 2304 halves
#define VT_BUFB (VT_BUF * 2)       // 4608 bytes

__global__ void __launch_bounds__(128, 8) attn_mma(const float* __restrict__ logit_scale)
{
    __shared__ __align__(16) uint16_t qs[2][QK_BUF];   // reused as V^T after QK
    __shared__ __align__(16) uint16_t ks[2][QK_BUF];

    int bh = blockIdx.x;
    int b = bh / NH, h = bh % NH;
    int tid = threadIdx.x, lane = tid & 31, warp = tid >> 5;
    int g = lane >> 2, t4 = lane & 3;
    float scale = __expf(fminf(logit_scale[h], LOG_MAX_SCALE));

    // ---- load + normalize + split q/k (rows < NT only; garbage rows are
    //      masked later, so no zero fill needed)
    for (int i = warp; i < NT; i += 4) {
        size_t off = (size_t)(b * NT + i) * QKVN + (size_t)h * HD + lane;
        float qv = g_qkv[off];
        float kv = g_qkv[off + CD];
        float sq = qv * qv;
        #pragma unroll
        for (int o = 16; o > 0; o >>= 1) sq += __shfl_xor_sync(0xffffffffu, sq, o);
        float qn = qv * (scale / (sqrtf(sq) + 1e-12f));
        float sk = kv * kv;
        #pragma unroll
        for (int o = 16; o > 0; o >>= 1) sk += __shfl_xor_sync(0xffffffffu, sk, o);
        float kn = kv / (sqrtf(sk) + 1e-12f);
        split_store(&qs[0][i * AQ_STR + lane], &qs[1][i * AQ_STR + lane], qn);
        split_store(&ks[0][i * AQ_STR + lane], &ks[1][i * AQ_STR + lane], kn);
    }
    __syncthreads();

    int r0 = warp * 16;
    // ---- QK^T
    float acc[8][4];
    #pragma unroll
    for (int nt = 0; nt < 8; nt++)
        #pragma unroll
        for (int q = 0; q < 4; q++) acc[nt][q] = 0.0f;

    uint32_t qaddr = smem_u32(qs) + (r0 + ((lane >> 3) & 1) * 8 + (lane & 7)) * 80
                   + (lane >> 4) * 16;
    uint32_t kaddr = smem_u32(ks) + (((lane >> 4) & 1) * 8 + (lane & 7)) * 80
                   + ((lane >> 3) & 1) * 16;

    #pragma unroll
    for (int ki = 0; ki < 2; ki++) {
        uint32_t ah[4], al[4];
        LDSM4(ah[0], ah[1], ah[2], ah[3], qaddr + ki * 32);
        LDSM4(al[0], al[1], al[2], al[3], qaddr + QK_BUFB + ki * 32);
        #pragma unroll
        for (int ntp = 0; ntp < 4; ntp++) {
            uint32_t bh_[4], bl_[4];
            LDSM4(bh_[0], bh_[1], bh_[2], bh_[3], kaddr + ntp * 16 * 80 + ki * 32);
            LDSM4(bl_[0], bl_[1], bl_[2], bl_[3], kaddr + QK_BUFB + ntp * 16 * 80 + ki * 32);
            #pragma unroll
            for (int sub = 0; sub < 2; sub++) {
                int nt = ntp * 2 + sub;
                uint32_t b0h = bh_[sub * 2], b1h = bh_[sub * 2 + 1];
                uint32_t b0l = bl_[sub * 2], b1l = bl_[sub * 2 + 1];
                mma_fp16(acc[nt], ah[0], ah[1], ah[2], ah[3], b0h, b1h);
                mma_fp16(acc[nt], ah[0], ah[1], ah[2], ah[3], b0l, b1l);
                mma_fp16(acc[nt], al[0], al[1], al[2], al[3], b0h, b1h);
            }
        }
    }
    __syncthreads();   // all warps done reading qs — safe to overlay V^T

    // ---- load + split V^T into qs overlay; zero tail cols (j=49..63)
    uint16_t* vt0 = &qs[0][0];
    uint16_t* vt1 = vt0 + VT_BUF;
    for (int i = warp; i < NT; i += 4) {
        float vv = g_qkv[(size_t)(b * NT + i) * QKVN + (size_t)h * HD + 2 * CD + lane];
        split_store(&vt0[lane * AV_STR + i], &vt1[lane * AV_STR + i], vv);
    }
    for (int u = tid; u < 32 * 15; u += 128) {
        int d = u / 15, j = 49 + (u % 15);
        vt0[d * AV_STR + j] = 0;
        vt1[d * AV_STR + j] = 0;
    }

    // ---- bias + mask + softmax (register-only; overlaps V-load latency)
    int rA = r0 + g, rB = rA + 8;
    int rAc = (rA < NT) ? rA : NT - 1;
    int rBc = (rB < NT) ? rB : NT - 1;
    const float* bias_h = g_bias + h * NT * NT;
    float mA = -1e30f, mB = -1e30f;
    #pragma unroll
    for (int nt = 0; nt < 8; nt++) {
        int c0 = nt * 8 + t4 * 2;
        int c0c = (c0 < NT) ? c0 : NT - 1;
        int c1c = (c0 + 1 < NT) ? c0 + 1 : NT - 1;
        float bA0 = __ldg(bias_h + rAc * NT + c0c);
        float bA1 = __ldg(bias_h + rAc * NT + c1c);
        float bB0 = __ldg(bias_h + rBc * NT + c0c);
        float bB1 = __ldg(bias_h + rBc * NT + c1c);
        acc[nt][0] = (c0 < NT) ? acc[nt][0] + bA0 : -1e30f;
        acc[nt][1] = (c0 + 1 < NT) ? acc[nt][1] + bA1 : -1e30f;
        acc[nt][2] = (c0 < NT) ? acc[nt][2] + bB0 : -1e30f;
        acc[nt][3] = (c0 + 1 < NT) ? acc[nt][3] + bB1 : -1e30f;
        mA = fmaxf(mA, fmaxf(acc[nt][0], acc[nt][1]));
        mB = fmaxf(mB, fmaxf(acc[nt][2], acc[nt][3]));
    }
    mA = fmaxf(mA, __shfl_xor_sync(0xffffffffu, mA, 1));
    mA = fmaxf(mA, __shfl_xor_sync(0xffffffffu, mA, 2));
    mB = fmaxf(mB, __shfl_xor_sync(0xffffffffu, mB, 1));
    mB = fmaxf(mB, __shfl_xor_sync(0xffffffffu, mB, 2));

    float sumA = 0.0f, sumB = 0.0f;
    #pragma unroll
    for (int nt = 0; nt < 8; nt++) {
        float p0 = __expf(acc[nt][0] - mA);
        float p1 = __expf(acc[nt][1] - mA);
        float p2 = __expf(acc[nt][2] - mB);
        float p3 = __expf(acc[nt][3] - mB);
        acc[nt][0] = p0; acc[nt][1] = p1; acc[nt][2] = p2; acc[nt][3] = p3;
        sumA += p0 + p1;
        sumB += p2 + p3;
    }
    sumA += __shfl_xor_sync(0xffffffffu, sumA, 1);
    sumA += __shfl_xor_sync(0xffffffffu, sumA, 2);
    sumB += __shfl_xor_sync(0xffffffffu, sumB, 1);
    sumB += __shfl_xor_sync(0xffffffffu, sumB, 2);
    float invA = __fdividef(1.0f, sumA);
    float invB = __fdividef(1.0f, sumB);

    __syncthreads();   // V^T ready

    // ---- PV
    float o[4][4];
    #pragma unroll
    for (int nd = 0; nd < 4; nd++)
        #pragma unroll
        for (int q = 0; q < 4; q++) o[nd][q] = 0.0f;

    uint32_t vaddr = smem_u32(qs) + (((lane >> 4) & 1) * 8 + (lane & 7)) * 144
                   + ((lane >> 3) & 1) * 16;

    #pragma unroll
    for (int js = 0; js < 4; js++) {
        uint32_t ph[4], pl[4];
        pack_hl(acc[2 * js][0],     acc[2 * js][1],     ph[0], pl[0]);
        pack_hl(acc[2 * js][2],     acc[2 * js][3],     ph[1], pl[1]);
        pack_hl(acc[2 * js + 1][0], acc[2 * js + 1][1], ph[2], pl[2]);
        pack_hl(acc[2 * js + 1][2], acc[2 * js + 1][3], ph[3], pl[3]);
        #pragma unroll
        for (int ndp = 0; ndp < 2; ndp++) {
            uint32_t vh_[4], vl_[4];
            LDSM4(vh_[0], vh_[1], vh_[2], vh_[3],
                  vaddr + ndp * 16 * 144 + js * 32);
            LDSM4(vl_[0], vl_[1], vl_[2], vl_[3],
                  vaddr + VT_BUFB + ndp * 16 * 144 + js * 32);
            #pragma unroll
            for (int sub = 0; sub < 2; sub++) {
                int nd = ndp * 2 + sub;
                uint32_t b0h = vh_[sub * 2], b1h = vh_[sub * 2 + 1];
                uint32_t b0l = vl_[sub * 2], b1l = vl_[sub * 2 + 1];
                mma_fp16(o[nd], ph[0], ph[1], ph[2], ph[3], b0h, b1h);
                mma_fp16(o[nd], ph[0], ph[1], ph[2], ph[3], b0l, b1l);
                mma_fp16(o[nd], pl[0], pl[1], pl[2], pl[3], b0h, b1h);
            }
        }
    }

    // ---- store
    if (rA < NT) {
        float* dst = g_ao + (size_t)(b * NT + rA) * CD + h * HD;
        #pragma unroll
        for (int nd = 0; nd < 4; nd++) {
            int d = nd * 8 + t4 * 2;
            *(float2*)(dst + d) = make_float2(o[nd][0] * invA, o[nd][1] * invA);
        }
    }
    if (rB < NT) {
        float* dst = g_ao + (size_t)(b * NT + rB) * CD + h * HD;
        #pragma unroll
        for (int nd = 0; nd < 4; nd++) {
            int d = nd * 8 + t4 * 2;
            *(float2*)(dst + d) = make_float2(o[nd][2] * invB, o[nd][3] * invB);
        }
    }
}

// ---------------------------------------------------------------------------
extern "C" void kernel_launch(void* const* d_in, const int* in_sizes, int n_in,
                              void* d_out, int out_size)
{
    const float* x           = (const float*)d_in[0];
    const float* qkv_w       = (const float*)d_in[1];
    const float* q_bias      = (const float*)d_in[2];
    const float* v_bias      = (const float*)d_in[3];
    const float* logit_scale = (const float*)d_in[4];
    const float* cpb_w1      = (const float*)d_in[5];
    const float* cpb_b1      = (const float*)d_in[6];
    const float* cpb_w2      = (const float*)d_in[7];
    const float* proj_w      = (const float*)d_in[8];
    const float* proj_b      = (const float*)d_in[9];
    float* out = (float*)d_out;

    void* p;
    cudaGetSymbolAddress(&p, g_qkv); float* qkv = (float*)p;
    cudaGetSymbolAddress(&p, g_ao);  float* ao  = (float*)p;

    cpb_mlp_kernel<<<TBL, 128>>>(cpb_w1, cpb_b1, cpb_w2);
    bias_expand_kernel<<<(NH * NT * NT + 255) / 256, 256>>>();

    dim3 gq(QKVN / 128, MROWS / 128);
    gemm_fp16<QKVN, 0><<<gq, 256>>>(x, qkv_w, qkv, q_bias, v_bias);

    attn_mma<<<BQ * NH, 128>>>(logit_scale);

    dim3 gp(CD / 128, MROWS / 128);
    gemm_fp16<CD, 1><<<gp, 256>>>(ao, proj_w, out, proj_b, nullptr);
}

// round 14
// speedup vs baseline: 1.2487x; 1.2487x over previous
#include <cuda_runtime.h>
#include <cuda_fp16.h>
#include <math.h>
#include <cstdint>
#include <cstddef>

#define BQ 2048
#define NT 49
#define CD 384
#define NH 12
#define HD 32
#define MROWS (BQ*NT)        // 100352
#define QKVN (3*CD)          // 1152
#define RPE 512
#define TBL 169
#define LOG_MAX_SCALE 4.60517018598809136804f

__device__ float g_qkv[(size_t)MROWS * QKVN];
__device__ float g_ao[(size_t)MROWS * CD];
__device__ float g_tab[TBL * NH];
__device__ float g_bias[NH * NT * NT];

// ---------------------------------------------------------------------------
__global__ void cpb_mlp_kernel(const float* __restrict__ w1,
                               const float* __restrict__ b1,
                               const float* __restrict__ w2)
{
    int i2 = blockIdx.x;
    int a = i2 / 13, bcol = i2 % 13;
    float vy = (float)(a - 6) * (8.0f / 6.0f);
    float vx = (float)(bcol - 6) * (8.0f / 6.0f);
    float t0 = copysignf(log2f(fabsf(vy) + 1.0f) / 3.0f, vy);
    float t1 = copysignf(log2f(fabsf(vx) + 1.0f) / 3.0f, vx);

    __shared__ float hidden[RPE];
    __shared__ float red[4];
    int tid = threadIdx.x;
    for (int r = tid; r < RPE; r += 128) {
        float hv = t0 * w1[2 * r] + t1 * w1[2 * r + 1] + b1[r];
        hidden[r] = fmaxf(hv, 0.0f);
    }
    __syncthreads();
    for (int h = 0; h < NH; h++) {
        float p = 0.0f;
        for (int r = tid; r < RPE; r += 128) p += hidden[r] * w2[h * RPE + r];
        #pragma unroll
        for (int o = 16; o > 0; o >>= 1) p += __shfl_xor_sync(0xffffffffu, p, o);
        if ((tid & 31) == 0) red[tid >> 5] = p;
        __syncthreads();
        if (tid == 0) g_tab[i2 * NH + h] = red[0] + red[1] + red[2] + red[3];
        __syncthreads();
    }
}

__global__ void bias_expand_kernel()
{
    int t = blockIdx.x * 256 + threadIdx.x;
    if (t >= NH * NT * NT) return;
    int h = t / (NT * NT);
    int ij = t % (NT * NT);
    int i = ij / NT, j = ij % NT;
    int rel = ((i / 7 - j / 7) + 6) * 13 + ((i % 7 - j % 7) + 6);
    float x = g_tab[rel * NH + h];
    g_bias[t] = 16.0f / (1.0f + __expf(-x));
}

// ---------------------------------------------------------------------------
// common MMA helpers
// ---------------------------------------------------------------------------
__device__ __forceinline__ uint32_t smem_u32(const void* p) {
    uint32_t a;
    asm("{ .reg .u64 t; cvta.to.shared.u64 t, %1; cvt.u32.u64 %0, t; }"
        : "=r"(a) : "l"(p));
    return a;
}

__device__ __forceinline__ uint2 pack4h(float4 v) {
    __half2 h0 = __floats2half2_rn(v.x, v.y);
    __half2 h1 = __floats2half2_rn(v.z, v.w);
    uint2 r;
    r.x = *(uint32_t*)&h0;
    r.y = *(uint32_t*)&h1;
    return r;
}

#define LDSM4(r0, r1, r2, r3, a) \
    asm volatile("ldmatrix.sync.aligned.m8n8.x4.shared.b16 {%0,%1,%2,%3}, [%4];" \
                 : "=r"(r0), "=r"(r1), "=r"(r2), "=r"(r3) : "r"(a))

__device__ __forceinline__ void mma_fp16(float c[4], uint32_t a0, uint32_t a1,
                                         uint32_t a2, uint32_t a3,
                                         uint32_t b0, uint32_t b1) {
    asm volatile(
        "mma.sync.aligned.m16n8k16.row.col.f32.f16.f16.f32 "
        "{%0,%1,%2,%3}, {%4,%5,%6,%7}, {%8,%9}, {%0,%1,%2,%3};"
        : "+f"(c[0]), "+f"(c[1]), "+f"(c[2]), "+f"(c[3])
        : "r"(a0), "r"(a1), "r"(a2), "r"(a3), "r"(b0), "r"(b1));
}

__device__ __forceinline__ void pack_hl(float f0, float f1, uint32_t& hi, uint32_t& lo) {
    __half h0 = __float2half_rn(f0), h1 = __float2half_rn(f1);
    __half l0 = __float2half_rn(f0 - __half2float(h0));
    __half l1 = __float2half_rn(f1 - __half2float(h1));
    hi = (uint32_t)(*(uint16_t*)&h0) | ((uint32_t)(*(uint16_t*)&h1) << 16);
    lo = (uint32_t)(*(uint16_t*)&l0) | ((uint32_t)(*(uint16_t*)&l1) << 16);
}

__device__ __forceinline__ void split_store(uint16_t* hi_p, uint16_t* lo_p, float f) {
    __half h = __float2half_rn(f);
    __half l = __float2half_rn(f - __half2float(h));
    *hi_p = *(uint16_t*)&h;
    *lo_p = *(uint16_t*)&l;
}

// ---------------------------------------------------------------------------
// FP16 tensor-core GEMM (double-buffered) — unchanged
// ---------------------------------------------------------------------------
#define HROW 40
#define BUFB (128 * HROW * 2)

template<int NC, int MODE>
__global__ void __launch_bounds__(256, 2) gemm_fp16(
    const float* __restrict__ A, const float* __restrict__ B,
    float* __restrict__ C,
    const float* __restrict__ bias0, const float* __restrict__ bias1)
{
    constexpr int K = 384;
    __shared__ __align__(16) uint16_t As[2][128 * HROW];
    __shared__ __align__(16) uint16_t Bs[2][128 * HROW];

    int tid = threadIdx.x;
    int lane = tid & 31, w = tid >> 5;
    int g = lane >> 2, t4 = lane & 3;
    int warp_m = (w >> 1) * 32;
    int warp_n = (w & 1) * 64;
    int m0 = blockIdx.y * 128;
    int n0 = blockIdx.x * 128;

    uint32_t as_u = smem_u32(As), bs_u = smem_u32(Bs);
    int arow = warp_m + ((lane >> 3) & 1) * 8 + (lane & 7);
    uint32_t aaddr = as_u + arow * 80 + (lane >> 4) * 16;
    int brow = warp_n + ((lane >> 4) & 1) * 8 + (lane & 7);
    uint32_t baddr = bs_u + brow * 80 + ((lane >> 3) & 1) * 16;

    int lr = tid >> 3;
    int lc = (tid & 7) * 4;

    const float* Ap = A + (size_t)(m0 + lr) * K + lc;
    const float* Bp = B + (size_t)(n0 + lr) * K + lc;

    float acc[2][8][4];
    #pragma unroll
    for (int mi = 0; mi < 2; mi++)
        #pragma unroll
        for (int ni = 0; ni < 8; ni++)
            #pragma unroll
            for (int q = 0; q < 4; q++) acc[mi][ni][q] = 0.0f;

    uint2 ra[4], rb[4];
    #pragma unroll
    for (int p = 0; p < 4; p++) {
        ra[p] = pack4h(*(const float4*)(Ap + (size_t)(32 * p) * K));
        rb[p] = pack4h(*(const float4*)(Bp + (size_t)(32 * p) * K));
    }
    #pragma unroll
    for (int p = 0; p < 4; p++) {
        int row = lr + 32 * p;
        *(uint2*)(As[0] + row * HROW + lc) = ra[p];
        *(uint2*)(Bs[0] + row * HROW + lc) = rb[p];
    }
    __syncthreads();

    int buf = 0;
    for (int k0 = 0; k0 < K; k0 += 32, buf ^= 1) {
        bool more = (k0 + 32 < K);
        if (more) {
            #pragma unroll
            for (int p = 0; p < 4; p++) {
                ra[p] = pack4h(*(const float4*)(Ap + (size_t)(32 * p) * K + (k0 + 32)));
                rb[p] = pack4h(*(const float4*)(Bp + (size_t)(32 * p) * K + (k0 + 32)));
            }
        }

        uint32_t ab = aaddr + buf * BUFB;
        uint32_t bb = baddr + buf * BUFB;
        #pragma unroll
        for (int kk = 0; kk < 2; kk++) {
            uint32_t kb = kk * 32;
            uint32_t af[2][4], bq[4][4];
            #pragma unroll
            for (int mi = 0; mi < 2; mi++)
                LDSM4(af[mi][0], af[mi][1], af[mi][2], af[mi][3],
                      ab + mi * 1280 + kb);
            #pragma unroll
            for (int p = 0; p < 4; p++)
                LDSM4(bq[p][0], bq[p][1], bq[p][2], bq[p][3],
                      bb + p * 1280 + kb);
            #pragma unroll
            for (int mi = 0; mi < 2; mi++)
                #pragma unroll
                for (int ni = 0; ni < 8; ni++) {
                    int p = ni >> 1, hsel = (ni & 1) * 2;
                    mma_fp16(acc[mi][ni], af[mi][0], af[mi][1], af[mi][2], af[mi][3],
                             bq[p][hsel], bq[p][hsel + 1]);
                }
        }

        if (more) {
            int nb = buf ^ 1;
            #pragma unroll
            for (int p = 0; p < 4; p++) {
                int row = lr + 32 * p;
                *(uint2*)(As[nb] + row * HROW + lc) = ra[p];
                *(uint2*)(Bs[nb] + row * HROW + lc) = rb[p];
            }
        }
        __syncthreads();
    }

    #pragma unroll
    for (int ni = 0; ni < 8; ni++) {
        int col = n0 + warp_n + ni * 8 + 2 * t4;
        float bx, by;
        if (MODE == 0) {
            bx = (col < CD) ? bias0[col] : ((col < 2 * CD) ? 0.0f : bias1[col - 2 * CD]);
            int c1 = col + 1;
            by = (c1 < CD) ? bias0[c1] : ((c1 < 2 * CD) ? 0.0f : bias1[c1 - 2 * CD]);
        } else {
            bx = bias0[col]; by = bias0[col + 1];
        }
        #pragma unroll
        for (int mi = 0; mi < 2; mi++) {
            int row = m0 + warp_m + mi * 16 + g;
            float2 o0 = make_float2(acc[mi][ni][0] + bx, acc[mi][ni][1] + by);
            float2 o1 = make_float2(acc[mi][ni][2] + bx, acc[mi][ni][3] + by);
            *(float2*)(C + (size_t)row * NC + col) = o0;
            *(float2*)(C + (size_t)(row + 8) * NC + col) = o1;
        }
    }
}

// ---------------------------------------------------------------------------
// MMA attention v3: float4 prologue (8 threads/row, packed STS.32 splits),
// V^T overlays q smem after QK, minimal zeroing. No forced min-blocks.
// ---------------------------------------------------------------------------
#define AQ_STR 40                  // halves per q/k row (32 + 8 pad), 80 B
#define AV_STR 72                  // halves per v^T row (64 + 8 pad), 144 B
#define QK_BUF (64 * AQ_STR)       // 2560 halves per split buffer
#define QK_BUFB (QK_BUF * 2)       // 5120 bytes
#define VT_BUF (32 * AV_STR)       // 2304 halves
#define VT_BUFB (VT_BUF * 2)       // 4608 bytes

__global__ void __launch_bounds__(128) attn_mma(const float* __restrict__ logit_scale)
{
    __shared__ __align__(16) uint16_t qs[2][QK_BUF];   // reused as V^T after QK
    __shared__ __align__(16) uint16_t ks[2][QK_BUF];

    int bh = blockIdx.x;
    int b = bh / NH, h = bh % NH;
    int tid = threadIdx.x, lane = tid & 31, warp = tid >> 5;
    int g = lane >> 2, t4 = lane & 3;
    float scale = __expf(fminf(logit_scale[h], LOG_MAX_SCALE));

    // ---- prologue: 8 threads per row, float4 loads, packed split stores
    int rip = tid >> 3;          // 0..15: row within pass
    int octl = tid & 7;          // 0..7: 4-float chunk within row
    #pragma unroll
    for (int p = 0; p < 4; p++) {
        int i = p * 16 + rip;
        int ic = (i < NT) ? i : NT - 1;           // clamp: all lanes load+shfl
        size_t off = (size_t)(b * NT + ic) * QKVN + (size_t)h * HD + octl * 4;
        float4 q4 = *(const float4*)(g_qkv + off);
        float4 k4 = *(const float4*)(g_qkv + off + CD);
        float sq = q4.x * q4.x + q4.y * q4.y + q4.z * q4.z + q4.w * q4.w;
        float sk = k4.x * k4.x + k4.y * k4.y + k4.z * k4.z + k4.w * k4.w;
        #pragma unroll
        for (int o = 1; o < 8; o <<= 1) {
            sq += __shfl_xor_sync(0xffffffffu, sq, o);
            sk += __shfl_xor_sync(0xffffffffu, sk, o);
        }
        if (i < NT) {
            float qsc = scale / (sqrtf(sq) + 1e-12f);
            float ksc = 1.0f / (sqrtf(sk) + 1e-12f);
            int bidx = i * AQ_STR + octl * 4;
            uint32_t hi, lo;
            pack_hl(q4.x * qsc, q4.y * qsc, hi, lo);
            *(uint32_t*)&qs[0][bidx] = hi;  *(uint32_t*)&qs[1][bidx] = lo;
            pack_hl(q4.z * qsc, q4.w * qsc, hi, lo);
            *(uint32_t*)&qs[0][bidx + 2] = hi;  *(uint32_t*)&qs[1][bidx + 2] = lo;
            pack_hl(k4.x * ksc, k4.y * ksc, hi, lo);
            *(uint32_t*)&ks[0][bidx] = hi;  *(uint32_t*)&ks[1][bidx] = lo;
            pack_hl(k4.z * ksc, k4.w * ksc, hi, lo);
            *(uint32_t*)&ks[0][bidx + 2] = hi;  *(uint32_t*)&ks[1][bidx + 2] = lo;
        }
    }
    __syncthreads();

    int r0 = warp * 16;
    // ---- QK^T
    float acc[8][4];
    #pragma unroll
    for (int nt = 0; nt < 8; nt++)
        #pragma unroll
        for (int q = 0; q < 4; q++) acc[nt][q] = 0.0f;

    uint32_t qaddr = smem_u32(qs) + (r0 + ((lane >> 3) & 1) * 8 + (lane & 7)) * 80
                   + (lane >> 4) * 16;
    uint32_t kaddr = smem_u32(ks) + (((lane >> 4) & 1) * 8 + (lane & 7)) * 80
                   + ((lane >> 3) & 1) * 16;

    #pragma unroll
    for (int ki = 0; ki < 2; ki++) {
        uint32_t ah[4], al[4];
        LDSM4(ah[0], ah[1], ah[2], ah[3], qaddr + ki * 32);
        LDSM4(al[0], al[1], al[2], al[3], qaddr + QK_BUFB + ki * 32);
        #pragma unroll
        for (int ntp = 0; ntp < 4; ntp++) {
            uint32_t bh_[4], bl_[4];
            LDSM4(bh_[0], bh_[1], bh_[2], bh_[3], kaddr + ntp * 16 * 80 + ki * 32);
            LDSM4(bl_[0], bl_[1], bl_[2], bl_[3], kaddr + QK_BUFB + ntp * 16 * 80 + ki * 32);
            #pragma unroll
            for (int sub = 0; sub < 2; sub++) {
                int nt = ntp * 2 + sub;
                uint32_t b0h = bh_[sub * 2], b1h = bh_[sub * 2 + 1];
                uint32_t b0l = bl_[sub * 2], b1l = bl_[sub * 2 + 1];
                mma_fp16(acc[nt], ah[0], ah[1], ah[2], ah[3], b0h, b1h);
                mma_fp16(acc[nt], ah[0], ah[1], ah[2], ah[3], b0l, b1l);
                mma_fp16(acc[nt], al[0], al[1], al[2], al[3], b0h, b1h);
            }
        }
    }
    __syncthreads();   // all warps done reading qs — safe to overlay V^T

    // ---- load + split V^T into qs overlay (float4); zero tail cols 49..63
    uint16_t* vt0 = &qs[0][0];
    uint16_t* vt1 = vt0 + VT_BUF;
    #pragma unroll
    for (int p = 0; p < 4; p++) {
        int i = p * 16 + rip;
        if (i < NT) {
            size_t off = (size_t)(b * NT + i) * QKVN + (size_t)h * HD + 2 * CD + octl * 4;
            float4 v4 = *(const float4*)(g_qkv + off);
            int d0 = octl * 4;
            split_store(&vt0[(d0 + 0) * AV_STR + i], &vt1[(d0 + 0) * AV_STR + i], v4.x);
            split_store(&vt0[(d0 + 1) * AV_STR + i], &vt1[(d0 + 1) * AV_STR + i], v4.y);
            split_store(&vt0[(d0 + 2) * AV_STR + i], &vt1[(d0 + 2) * AV_STR + i], v4.z);
            split_store(&vt0[(d0 + 3) * AV_STR + i], &vt1[(d0 + 3) * AV_STR + i], v4.w);
        }
    }
    for (int u = tid; u < 32 * 15; u += 128) {
        int d = u / 15, j = 49 + (u % 15);
        vt0[d * AV_STR + j] = 0;
        vt1[d * AV_STR + j] = 0;
    }

    // ---- bias + mask + softmax (register-only; overlaps V-load latency)
    int rA = r0 + g, rB = rA + 8;
    int rAc = (rA < NT) ? rA : NT - 1;
    int rBc = (rB < NT) ? rB : NT - 1;
    const float* bias_h = g_bias + h * NT * NT;
    float mA = -1e30f, mB = -1e30f;
    #pragma unroll
    for (int nt = 0; nt < 8; nt++) {
        int c0 = nt * 8 + t4 * 2;
        int c0c = (c0 < NT) ? c0 : NT - 1;
        int c1c = (c0 + 1 < NT) ? c0 + 1 : NT - 1;
        float bA0 = __ldg(bias_h + rAc * NT + c0c);
        float bA1 = __ldg(bias_h + rAc * NT + c1c);
        float bB0 = __ldg(bias_h + rBc * NT + c0c);
        float bB1 = __ldg(bias_h + rBc * NT + c1c);
        acc[nt][0] = (c0 < NT) ? acc[nt][0] + bA0 : -1e30f;
        acc[nt][1] = (c0 + 1 < NT) ? acc[nt][1] + bA1 : -1e30f;
        acc[nt][2] = (c0 < NT) ? acc[nt][2] + bB0 : -1e30f;
        acc[nt][3] = (c0 + 1 < NT) ? acc[nt][3] + bB1 : -1e30f;
        mA = fmaxf(mA, fmaxf(acc[nt][0], acc[nt][1]));
        mB = fmaxf(mB, fmaxf(acc[nt][2], acc[nt][3]));
    }
    mA = fmaxf(mA, __shfl_xor_sync(0xffffffffu, mA, 1));
    mA = fmaxf(mA, __shfl_xor_sync(0xffffffffu, mA, 2));
    mB = fmaxf(mB, __shfl_xor_sync(0xffffffffu, mB, 1));
    mB = fmaxf(mB, __shfl_xor_sync(0xffffffffu, mB, 2));

    float sumA = 0.0f, sumB = 0.0f;
    #pragma unroll
    for (int nt = 0; nt < 8; nt++) {
        float p0 = __expf(acc[nt][0] - mA);
        float p1 = __expf(acc[nt][1] - mA);
        float p2 = __expf(acc[nt][2] - mB);
        float p3 = __expf(acc[nt][3] - mB);
        acc[nt][0] = p0; acc[nt][1] = p1; acc[nt][2] = p2; acc[nt][3] = p3;
        sumA += p0 + p1;
        sumB += p2 + p3;
    }
    sumA += __shfl_xor_sync(0xffffffffu, sumA, 1);
    sumA += __shfl_xor_sync(0xffffffffu, sumA, 2);
    sumB += __shfl_xor_sync(0xffffffffu, sumB, 1);
    sumB += __shfl_xor_sync(0xffffffffu, sumB, 2);
    float invA = __fdividef(1.0f, sumA);
    float invB = __fdividef(1.0f, sumB);

    __syncthreads();   // V^T ready

    // ---- PV
    float o[4][4];
    #pragma unroll
    for (int nd = 0; nd < 4; nd++)
        #pragma unroll
        for (int q = 0; q < 4; q++) o[nd][q] = 0.0f;

    uint32_t vaddr = smem_u32(qs) + (((lane >> 4) & 1) * 8 + (lane & 7)) * 144
                   + ((lane >> 3) & 1) * 16;

    #pragma unroll
    for (int js = 0; js < 4; js++) {
        uint32_t ph[4], pl[4];
        pack_hl(acc[2 * js][0],     acc[2 * js][1],     ph[0], pl[0]);
        pack_hl(acc[2 * js][2],     acc[2 * js][3],     ph[1], pl[1]);
        pack_hl(acc[2 * js + 1][0], acc[2 * js + 1][1], ph[2], pl[2]);
        pack_hl(acc[2 * js + 1][2], acc[2 * js + 1][3], ph[3], pl[3]);
        #pragma unroll
        for (int ndp = 0; ndp < 2; ndp++) {
            uint32_t vh_[4], vl_[4];
            LDSM4(vh_[0], vh_[1], vh_[2], vh_[3],
                  vaddr + ndp * 16 * 144 + js * 32);
            LDSM4(vl_[0], vl_[1], vl_[2], vl_[3],
                  vaddr + VT_BUFB + ndp * 16 * 144 + js * 32);
            #pragma unroll
            for (int sub = 0; sub < 2; sub++) {
                int nd = ndp * 2 + sub;
                uint32_t b0h = vh_[sub * 2], b1h = vh_[sub * 2 + 1];
                uint32_t b0l = vl_[sub * 2], b1l = vl_[sub * 2 + 1];
                mma_fp16(o[nd], ph[0], ph[1], ph[2], ph[3], b0h, b1h);
                mma_fp16(o[nd], ph[0], ph[1], ph[2], ph[3], b0l, b1l);
                mma_fp16(o[nd], pl[0], pl[1], pl[2], pl[3], b0h, b1h);
            }
        }
    }

    // ---- store
    if (rA < NT) {
        float* dst = g_ao + (size_t)(b * NT + rA) * CD + h * HD;
        #pragma unroll
        for (int nd = 0; nd < 4; nd++) {
            int d = nd * 8 + t4 * 2;
            *(float2*)(dst + d) = make_float2(o[nd][0] * invA, o[nd][1] * invA);
        }
    }
    if (rB < NT) {
        float* dst = g_ao + (size_t)(b * NT + rB) * CD + h * HD;
        #pragma unroll
        for (int nd = 0; nd < 4; nd++) {
            int d = nd * 8 + t4 * 2;
            *(float2*)(dst + d) = make_float2(o[nd][2] * invB, o[nd][3] * invB);
        }
    }
}

// ---------------------------------------------------------------------------
extern "C" void kernel_launch(void* const* d_in, const int* in_sizes, int n_in,
                              void* d_out, int out_size)
{
    const float* x           = (const float*)d_in[0];
    const float* qkv_w       = (const float*)d_in[1];
    const float* q_bias      = (const float*)d_in[2];
    const float* v_bias      = (const float*)d_in[3];
    const float* logit_scale = (const float*)d_in[4];
    const float* cpb_w1      = (const float*)d_in[5];
    const float* cpb_b1      = (const float*)d_in[6];
    const float* cpb_w2      = (const float*)d_in[7];
    const float* proj_w      = (const float*)d_in[8];
    const float* proj_b      = (const float*)d_in[9];
    float* out = (float*)d_out;

    void* p;
    cudaGetSymbolAddress(&p, g_qkv); float* qkv = (float*)p;
    cudaGetSymbolAddress(&p, g_ao);  float* ao  = (float*)p;

    cpb_mlp_kernel<<<TBL, 128>>>(cpb_w1, cpb_b1, cpb_w2);
    bias_expand_kernel<<<(NH * NT * NT + 255) / 256, 256>>>();

    dim3 gq(QKVN / 128, MROWS / 128);
    gemm_fp16<QKVN, 0><<<gq, 256>>>(x, qkv_w, qkv, q_bias, v_bias);

    attn_mma<<<BQ * NH, 128>>>(logit_scale);

    dim3 gp(CD / 128, MROWS / 128);
    gemm_fp16<CD, 1><<<gp, 256>>>(ao, proj_w, out, proj_b, nullptr);
}

// round 15
// speedup vs baseline: 1.3256x; 1.0616x over previous
#include <cuda_runtime.h>
#include <cuda_fp16.h>
#include <math.h>
#include <cstdint>
#include <cstddef>

#define BQ 2048
#define NT 49
#define CD 384
#define NH 12
#define HD 32
#define MROWS (BQ*NT)        // 100352
#define QKVN (3*CD)          // 1152
#define RPE 512
#define TBL 169
#define LOG_MAX_SCALE 4.60517018598809136804f

__device__ float  g_qkv[(size_t)MROWS * QKVN];   // fp32 qkv (attn needs fp32 q/k)
__device__ __half g_xh[(size_t)MROWS * CD];      // fp16 x
__device__ __half g_aoh[(size_t)MROWS * CD];     // fp16 attention output
__device__ __half g_wqh[QKVN * CD];              // fp16 qkv_w
__device__ __half g_wph[CD * CD];                // fp16 proj_w
__device__ float  g_tab[TBL * NH];
__device__ float  g_bias[NH * NT * NT];

// ---------------------------------------------------------------------------
__global__ void cpb_mlp_kernel(const float* __restrict__ w1,
                               const float* __restrict__ b1,
                               const float* __restrict__ w2)
{
    int i2 = blockIdx.x;
    int a = i2 / 13, bcol = i2 % 13;
    float vy = (float)(a - 6) * (8.0f / 6.0f);
    float vx = (float)(bcol - 6) * (8.0f / 6.0f);
    float t0 = copysignf(log2f(fabsf(vy) + 1.0f) / 3.0f, vy);
    float t1 = copysignf(log2f(fabsf(vx) + 1.0f) / 3.0f, vx);

    __shared__ float hidden[RPE];
    __shared__ float red[4];
    int tid = threadIdx.x;
    for (int r = tid; r < RPE; r += 128) {
        float hv = t0 * w1[2 * r] + t1 * w1[2 * r + 1] + b1[r];
        hidden[r] = fmaxf(hv, 0.0f);
    }
    __syncthreads();
    for (int h = 0; h < NH; h++) {
        float p = 0.0f;
        for (int r = tid; r < RPE; r += 128) p += hidden[r] * w2[h * RPE + r];
        #pragma unroll
        for (int o = 16; o > 0; o >>= 1) p += __shfl_xor_sync(0xffffffffu, p, o);
        if ((tid & 31) == 0) red[tid >> 5] = p;
        __syncthreads();
        if (tid == 0) g_tab[i2 * NH + h] = red[0] + red[1] + red[2] + red[3];
        __syncthreads();
    }
}

__global__ void bias_expand_kernel()
{
    int t = blockIdx.x * 256 + threadIdx.x;
    if (t >= NH * NT * NT) return;
    int h = t / (NT * NT);
    int ij = t % (NT * NT);
    int i = ij / NT, j = ij % NT;
    int rel = ((i / 7 - j / 7) + 6) * 13 + ((i % 7 - j % 7) + 6);
    float x = g_tab[rel * NH + h];
    g_bias[t] = 16.0f / (1.0f + __expf(-x));
}

// ---------------------------------------------------------------------------
// common helpers
// ---------------------------------------------------------------------------
__device__ __forceinline__ uint32_t smem_u32(const void* p) {
    uint32_t a;
    asm("{ .reg .u64 t; cvta.to.shared.u64 t, %1; cvt.u32.u64 %0, t; }"
        : "=r"(a) : "l"(p));
    return a;
}

__device__ __forceinline__ uint2 pack4h(float4 v) {
    __half2 h0 = __floats2half2_rn(v.x, v.y);
    __half2 h1 = __floats2half2_rn(v.z, v.w);
    uint2 r;
    r.x = *(uint32_t*)&h0;
    r.y = *(uint32_t*)&h1;
    return r;
}

#define LDSM4(r0, r1, r2, r3, a) \
    asm volatile("ldmatrix.sync.aligned.m8n8.x4.shared.b16 {%0,%1,%2,%3}, [%4];" \
                 : "=r"(r0), "=r"(r1), "=r"(r2), "=r"(r3) : "r"(a))

__device__ __forceinline__ void mma_fp16(float c[4], uint32_t a0, uint32_t a1,
                                         uint32_t a2, uint32_t a3,
                                         uint32_t b0, uint32_t b1) {
    asm volatile(
        "mma.sync.aligned.m16n8k16.row.col.f32.f16.f16.f32 "
        "{%0,%1,%2,%3}, {%4,%5,%6,%7}, {%8,%9}, {%0,%1,%2,%3};"
        : "+f"(c[0]), "+f"(c[1]), "+f"(c[2]), "+f"(c[3])
        : "r"(a0), "r"(a1), "r"(a2), "r"(a3), "r"(b0), "r"(b1));
}

__device__ __forceinline__ void pack_hl(float f0, float f1, uint32_t& hi, uint32_t& lo) {
    __half h0 = __float2half_rn(f0), h1 = __float2half_rn(f1);
    __half l0 = __float2half_rn(f0 - __half2float(h0));
    __half l1 = __float2half_rn(f1 - __half2float(h1));
    hi = (uint32_t)(*(uint16_t*)&h0) | ((uint32_t)(*(uint16_t*)&h1) << 16);
    lo = (uint32_t)(*(uint16_t*)&l0) | ((uint32_t)(*(uint16_t*)&l1) << 16);
}

__device__ __forceinline__ void split_store(uint16_t* hi_p, uint16_t* lo_p, float f) {
    __half h = __float2half_rn(f);
    __half l = __float2half_rn(f - __half2float(h));
    *hi_p = *(uint16_t*)&h;
    *lo_p = *(uint16_t*)&l;
}

#define CP16(dst, src) \
    asm volatile("cp.async.cg.shared.global [%0], [%1], 16;" :: "r"(dst), "l"(src))
#define CP_COMMIT() asm volatile("cp.async.commit_group;" ::: "memory")
#define CP_WAIT(n)  asm volatile("cp.async.wait_group %0;" :: "n"(n) : "memory")

// ---------------------------------------------------------------------------
// fp32 -> fp16 convert (elementwise, float4 granularity)
// ---------------------------------------------------------------------------
__global__ void cvt_half_kernel(const float* __restrict__ s, __half* __restrict__ d, int n4)
{
    int i = blockIdx.x * 256 + threadIdx.x;
    if (i < n4) {
        float4 v = ((const float4*)s)[i];
        ((uint2*)d)[i] = pack4h(v);
    }
}

// ---------------------------------------------------------------------------
// FP16 tensor-core GEMM with cp.async staging (fp16 in gmem, fp32 accum).
// C[M,NC] = A[M,384] @ B[NC,384]^T + bias. 128x128 CTA tile, BK=32 double-buf.
// ---------------------------------------------------------------------------
#define HROW 40                       // halves per smem row (32 data + 8 pad)
#define BUFB (128 * HROW * 2)         // bytes per buffer per matrix (10240)

template<int NC, int MODE>
__global__ void __launch_bounds__(256) gemm_fp16cp(
    const __half* __restrict__ A, const __half* __restrict__ B,
    float* __restrict__ C,
    const float* __restrict__ bias0, const float* __restrict__ bias1)
{
    constexpr int K = 384;
    constexpr int NSTAGE = 12;
    __shared__ __align__(16) uint16_t As[2][128 * HROW];
    __shared__ __align__(16) uint16_t Bs[2][128 * HROW];

    int tid = threadIdx.x;
    int lane = tid & 31, w = tid >> 5;
    int g = lane >> 2, t4 = lane & 3;
    int warp_m = (w >> 1) * 32;
    int warp_n = (w & 1) * 64;
    int m0 = blockIdx.y * 128;
    int n0 = blockIdx.x * 128;

    uint32_t as_u = smem_u32(As), bs_u = smem_u32(Bs);
    int arow = warp_m + ((lane >> 3) & 1) * 8 + (lane & 7);
    uint32_t aaddr = as_u + arow * 80 + (lane >> 4) * 16;
    int brow = warp_n + ((lane >> 4) & 1) * 8 + (lane & 7);
    uint32_t baddr = bs_u + brow * 80 + ((lane >> 3) & 1) * 16;

    // cp.async mapping: 4 threads per row (16B each), rows tid>>2 and +64
    int crow = tid >> 2, cseg = tid & 3;
    const __half* Asrc = A + (size_t)(m0 + crow) * K + cseg * 8;
    const __half* Bsrc = B + (size_t)(n0 + crow) * K + cseg * 8;
    uint32_t adst = as_u + crow * 80 + cseg * 16;
    uint32_t bdst = bs_u + crow * 80 + cseg * 16;

    float acc[2][8][4];
    #pragma unroll
    for (int mi = 0; mi < 2; mi++)
        #pragma unroll
        for (int ni = 0; ni < 8; ni++)
            #pragma unroll
            for (int q = 0; q < 4; q++) acc[mi][ni][q] = 0.0f;

    // prologue: issue stages 0 and 1
    #pragma unroll
    for (int s0 = 0; s0 < 2; s0++) {
        CP16(adst + s0 * BUFB, Asrc + s0 * 32);
        CP16(adst + s0 * BUFB + 64 * 80, Asrc + (size_t)64 * K + s0 * 32);
        CP16(bdst + s0 * BUFB, Bsrc + s0 * 32);
        CP16(bdst + s0 * BUFB + 64 * 80, Bsrc + (size_t)64 * K + s0 * 32);
        CP_COMMIT();
    }

    for (int s = 0; s < NSTAGE; s++) {
        if (s < NSTAGE - 1) { CP_WAIT(1); } else { CP_WAIT(0); }
        __syncthreads();

        int buf = s & 1;
        uint32_t ab = aaddr + buf * BUFB;
        uint32_t bb = baddr + buf * BUFB;
        #pragma unroll
        for (int kk = 0; kk < 2; kk++) {
            uint32_t kb = kk * 32;
            uint32_t af[2][4], bq[4][4];
            #pragma unroll
            for (int mi = 0; mi < 2; mi++)
                LDSM4(af[mi][0], af[mi][1], af[mi][2], af[mi][3],
                      ab + mi * 1280 + kb);
            #pragma unroll
            for (int p = 0; p < 4; p++)
                LDSM4(bq[p][0], bq[p][1], bq[p][2], bq[p][3],
                      bb + p * 1280 + kb);
            #pragma unroll
            for (int mi = 0; mi < 2; mi++)
                #pragma unroll
                for (int ni = 0; ni < 8; ni++) {
                    int p = ni >> 1, hsel = (ni & 1) * 2;
                    mma_fp16(acc[mi][ni], af[mi][0], af[mi][1], af[mi][2], af[mi][3],
                             bq[p][hsel], bq[p][hsel + 1]);
                }
        }
        __syncthreads();

        if (s + 2 < NSTAGE) {
            int nb = s & 1;    // buffer just freed
            const __half* As2 = Asrc + (s + 2) * 32;
            const __half* Bs2 = Bsrc + (s + 2) * 32;
            CP16(adst + nb * BUFB, As2);
            CP16(adst + nb * BUFB + 64 * 80, As2 + (size_t)64 * K);
            CP16(bdst + nb * BUFB, Bs2);
            CP16(bdst + nb * BUFB + 64 * 80, Bs2 + (size_t)64 * K);
            CP_COMMIT();
        }
    }

    #pragma unroll
    for (int ni = 0; ni < 8; ni++) {
        int col = n0 + warp_n + ni * 8 + 2 * t4;
        float bx, by;
        if (MODE == 0) {
            bx = (col < CD) ? bias0[col] : ((col < 2 * CD) ? 0.0f : bias1[col - 2 * CD]);
            int c1 = col + 1;
            by = (c1 < CD) ? bias0[c1] : ((c1 < 2 * CD) ? 0.0f : bias1[c1 - 2 * CD]);
        } else {
            bx = bias0[col]; by = bias0[col + 1];
        }
        #pragma unroll
        for (int mi = 0; mi < 2; mi++) {
            int row = m0 + warp_m + mi * 16 + g;
            float2 o0 = make_float2(acc[mi][ni][0] + bx, acc[mi][ni][1] + by);
            float2 o1 = make_float2(acc[mi][ni][2] + bx, acc[mi][ni][3] + by);
            *(float2*)(C + (size_t)row * NC + col) = o0;
            *(float2*)(C + (size_t)(row + 8) * NC + col) = o1;
        }
    }
}

// ---------------------------------------------------------------------------
// MMA attention v3 (round-14 winner) + fp16 output stores.
// ---------------------------------------------------------------------------
#define AQ_STR 40
#define AV_STR 72
#define QK_BUF (64 * AQ_STR)
#define QK_BUFB (QK_BUF * 2)
#define VT_BUF (32 * AV_STR)
#define VT_BUFB (VT_BUF * 2)

__global__ void __launch_bounds__(128) attn_mma(const float* __restrict__ logit_scale)
{
    __shared__ __align__(16) uint16_t qs[2][QK_BUF];   // reused as V^T after QK
    __shared__ __align__(16) uint16_t ks[2][QK_BUF];

    int bh = blockIdx.x;
    int b = bh / NH, h = bh % NH;
    int tid = threadIdx.x, lane = tid & 31, warp = tid >> 5;
    int g = lane >> 2, t4 = lane & 3;
    float scale = __expf(fminf(logit_scale[h], LOG_MAX_SCALE));

    // ---- prologue: 8 threads per row, float4 loads, packed split stores
    int rip = tid >> 3;
    int octl = tid & 7;
    #pragma unroll
    for (int p = 0; p < 4; p++) {
        int i = p * 16 + rip;
        int ic = (i < NT) ? i : NT - 1;
        size_t off = (size_t)(b * NT + ic) * QKVN + (size_t)h * HD + octl * 4;
        float4 q4 = *(const float4*)(g_qkv + off);
        float4 k4 = *(const float4*)(g_qkv + off + CD);
        float sq = q4.x * q4.x + q4.y * q4.y + q4.z * q4.z + q4.w * q4.w;
        float sk = k4.x * k4.x + k4.y * k4.y + k4.z * k4.z + k4.w * k4.w;
        #pragma unroll
        for (int o = 1; o < 8; o <<= 1) {
            sq += __shfl_xor_sync(0xffffffffu, sq, o);
            sk += __shfl_xor_sync(0xffffffffu, sk, o);
        }
        if (i < NT) {
            float qsc = scale / (sqrtf(sq) + 1e-12f);
            float ksc = 1.0f / (sqrtf(sk) + 1e-12f);
            int bidx = i * AQ_STR + octl * 4;
            uint32_t hi, lo;
            pack_hl(q4.x * qsc, q4.y * qsc, hi, lo);
            *(uint32_t*)&qs[0][bidx] = hi;  *(uint32_t*)&qs[1][bidx] = lo;
            pack_hl(q4.z * qsc, q4.w * qsc, hi, lo);
            *(uint32_t*)&qs[0][bidx + 2] = hi;  *(uint32_t*)&qs[1][bidx + 2] = lo;
            pack_hl(k4.x * ksc, k4.y * ksc, hi, lo);
            *(uint32_t*)&ks[0][bidx] = hi;  *(uint32_t*)&ks[1][bidx] = lo;
            pack_hl(k4.z * ksc, k4.w * ksc, hi, lo);
            *(uint32_t*)&ks[0][bidx + 2] = hi;  *(uint32_t*)&ks[1][bidx + 2] = lo;
        }
    }
    __syncthreads();

    int r0 = warp * 16;
    float acc[8][4];
    #pragma unroll
    for (int nt = 0; nt < 8; nt++)
        #pragma unroll
        for (int q = 0; q < 4; q++) acc[nt][q] = 0.0f;

    uint32_t qaddr = smem_u32(qs) + (r0 + ((lane >> 3) & 1) * 8 + (lane & 7)) * 80
                   + (lane >> 4) * 16;
    uint32_t kaddr = smem_u32(ks) + (((lane >> 4) & 1) * 8 + (lane & 7)) * 80
                   + ((lane >> 3) & 1) * 16;

    #pragma unroll
    for (int ki = 0; ki < 2; ki++) {
        uint32_t ah[4], al[4];
        LDSM4(ah[0], ah[1], ah[2], ah[3], qaddr + ki * 32);
        LDSM4(al[0], al[1], al[2], al[3], qaddr + QK_BUFB + ki * 32);
        #pragma unroll
        for (int ntp = 0; ntp < 4; ntp++) {
            uint32_t bh_[4], bl_[4];
            LDSM4(bh_[0], bh_[1], bh_[2], bh_[3], kaddr + ntp * 16 * 80 + ki * 32);
            LDSM4(bl_[0], bl_[1], bl_[2], bl_[3], kaddr + QK_BUFB + ntp * 16 * 80 + ki * 32);
            #pragma unroll
            for (int sub = 0; sub < 2; sub++) {
                int nt = ntp * 2 + sub;
                uint32_t b0h = bh_[sub * 2], b1h = bh_[sub * 2 + 1];
                uint32_t b0l = bl_[sub * 2], b1l = bl_[sub * 2 + 1];
                mma_fp16(acc[nt], ah[0], ah[1], ah[2], ah[3], b0h, b1h);
                mma_fp16(acc[nt], ah[0], ah[1], ah[2], ah[3], b0l, b1l);
                mma_fp16(acc[nt], al[0], al[1], al[2], al[3], b0h, b1h);
            }
        }
    }
    __syncthreads();

    // ---- load + split V^T into qs overlay (float4); zero tail cols 49..63
    uint16_t* vt0 = &qs[0][0];
    uint16_t* vt1 = vt0 + VT_BUF;
    #pragma unroll
    for (int p = 0; p < 4; p++) {
        int i = p * 16 + rip;
        if (i < NT) {
            size_t off = (size_t)(b * NT + i) * QKVN + (size_t)h * HD + 2 * CD + octl * 4;
            float4 v4 = *(const float4*)(g_qkv + off);
            int d0 = octl * 4;
            split_store(&vt0[(d0 + 0) * AV_STR + i], &vt1[(d0 + 0) * AV_STR + i], v4.x);
            split_store(&vt0[(d0 + 1) * AV_STR + i], &vt1[(d0 + 1) * AV_STR + i], v4.y);
            split_store(&vt0[(d0 + 2) * AV_STR + i], &vt1[(d0 + 2) * AV_STR + i], v4.z);
            split_store(&vt0[(d0 + 3) * AV_STR + i], &vt1[(d0 + 3) * AV_STR + i], v4.w);
        }
    }
    for (int u = tid; u < 32 * 15; u += 128) {
        int d = u / 15, j = 49 + (u % 15);
        vt0[d * AV_STR + j] = 0;
        vt1[d * AV_STR + j] = 0;
    }

    // ---- bias + mask + softmax
    int rA = r0 + g, rB = rA + 8;
    int rAc = (rA < NT) ? rA : NT - 1;
    int rBc = (rB < NT) ? rB : NT - 1;
    const float* bias_h = g_bias + h * NT * NT;
    float mA = -1e30f, mB = -1e30f;
    #pragma unroll
    for (int nt = 0; nt < 8; nt++) {
        int c0 = nt * 8 + t4 * 2;
        int c0c = (c0 < NT) ? c0 : NT - 1;
        int c1c = (c0 + 1 < NT) ? c0 + 1 : NT - 1;
        float bA0 = __ldg(bias_h + rAc * NT + c0c);
        float bA1 = __ldg(bias_h + rAc * NT + c1c);
        float bB0 = __ldg(bias_h + rBc * NT + c0c);
        float bB1 = __ldg(bias_h + rBc * NT + c1c);
        acc[nt][0] = (c0 < NT) ? acc[nt][0] + bA0 : -1e30f;
        acc[nt][1] = (c0 + 1 < NT) ? acc[nt][1] + bA1 : -1e30f;
        acc[nt][2] = (c0 < NT) ? acc[nt][2] + bB0 : -1e30f;
        acc[nt][3] = (c0 + 1 < NT) ? acc[nt][3] + bB1 : -1e30f;
        mA = fmaxf(mA, fmaxf(acc[nt][0], acc[nt][1]));
        mB = fmaxf(mB, fmaxf(acc[nt][2], acc[nt][3]));
    }
    mA = fmaxf(mA, __shfl_xor_sync(0xffffffffu, mA, 1));
    mA = fmaxf(mA, __shfl_xor_sync(0xffffffffu, mA, 2));
    mB = fmaxf(mB, __shfl_xor_sync(0xffffffffu, mB, 1));
    mB = fmaxf(mB, __shfl_xor_sync(0xffffffffu, mB, 2));

    float sumA = 0.0f, sumB = 0.0f;
    #pragma unroll
    for (int nt = 0; nt < 8; nt++) {
        float p0 = __expf(acc[nt][0] - mA);
        float p1 = __expf(acc[nt][1] - mA);
        float p2 = __expf(acc[nt][2] - mB);
        float p3 = __expf(acc[nt][3] - mB);
        acc[nt][0] = p0; acc[nt][1] = p1; acc[nt][2] = p2; acc[nt][3] = p3;
        sumA += p0 + p1;
        sumB += p2 + p3;
    }
    sumA += __shfl_xor_sync(0xffffffffu, sumA, 1);
    sumA += __shfl_xor_sync(0xffffffffu, sumA, 2);
    sumB += __shfl_xor_sync(0xffffffffu, sumB, 1);
    sumB += __shfl_xor_sync(0xffffffffu, sumB, 2);
    float invA = __fdividef(1.0f, sumA);
    float invB = __fdividef(1.0f, sumB);

    __syncthreads();   // V^T ready

    // ---- PV
    float o[4][4];
    #pragma unroll
    for (int nd = 0; nd < 4; nd++)
        #pragma unroll
        for (int q = 0; q < 4; q++) o[nd][q] = 0.0f;

    uint32_t vaddr = smem_u32(qs) + (((lane >> 4) & 1) * 8 + (lane & 7)) * 144
                   + ((lane >> 3) & 1) * 16;

    #pragma unroll
    for (int js = 0; js < 4; js++) {
        uint32_t ph[4], pl[4];
        pack_hl(acc[2 * js][0],     acc[2 * js][1],     ph[0], pl[0]);
        pack_hl(acc[2 * js][2],     acc[2 * js][3],     ph[1], pl[1]);
        pack_hl(acc[2 * js + 1][0], acc[2 * js + 1][1], ph[2], pl[2]);
        pack_hl(acc[2 * js + 1][2], acc[2 * js + 1][3], ph[3], pl[3]);
        #pragma unroll
        for (int ndp = 0; ndp < 2; ndp++) {
            uint32_t vh_[4], vl_[4];
            LDSM4(vh_[0], vh_[1], vh_[2], vh_[3],
                  vaddr + ndp * 16 * 144 + js * 32);
            LDSM4(vl_[0], vl_[1], vl_[2], vl_[3],
                  vaddr + VT_BUFB + ndp * 16 * 144 + js * 32);
            #pragma unroll
            for (int sub = 0; sub < 2; sub++) {
                int nd = ndp * 2 + sub;
                uint32_t b0h = vh_[sub * 2], b1h = vh_[sub * 2 + 1];
                uint32_t b0l = vl_[sub * 2], b1l = vl_[sub * 2 + 1];
                mma_fp16(o[nd], ph[0], ph[1], ph[2], ph[3], b0h, b1h);
                mma_fp16(o[nd], ph[0], ph[1], ph[2], ph[3], b0l, b1l);
                mma_fp16(o[nd], pl[0], pl[1], pl[2], pl[3], b0h, b1h);
            }
        }
    }

    // ---- store fp16 (half2)
    if (rA < NT) {
        __half* dst = g_aoh + (size_t)(b * NT + rA) * CD + h * HD;
        #pragma unroll
        for (int nd = 0; nd < 4; nd++) {
            int d = nd * 8 + t4 * 2;
            __half2 hv = __floats2half2_rn(o[nd][0] * invA, o[nd][1] * invA);
            *(__half2*)(dst + d) = hv;
        }
    }
    if (rB < NT) {
        __half* dst = g_aoh + (size_t)(b * NT + rB) * CD + h * HD;
        #pragma unroll
        for (int nd = 0; nd < 4; nd++) {
            int d = nd * 8 + t4 * 2;
            __half2 hv = __floats2half2_rn(o[nd][2] * invB, o[nd][3] * invB);
            *(__half2*)(dst + d) = hv;
        }
    }
}

// ---------------------------------------------------------------------------
extern "C" void kernel_launch(void* const* d_in, const int* in_sizes, int n_in,
                              void* d_out, int out_size)
{
    const float* x           = (const float*)d_in[0];
    const float* qkv_w       = (const float*)d_in[1];
    const float* q_bias      = (const float*)d_in[2];
    const float* v_bias      = (const float*)d_in[3];
    const float* logit_scale = (const float*)d_in[4];
    const float* cpb_w1      = (const float*)d_in[5];
    const float* cpb_b1      = (const float*)d_in[6];
    const float* cpb_w2      = (const float*)d_in[7];
    const float* proj_w      = (const float*)d_in[8];
    const float* proj_b      = (const float*)d_in[9];
    float* out = (float*)d_out;

    void* p;
    cudaGetSymbolAddress(&p, g_qkv); float*  qkv = (float*)p;
    cudaGetSymbolAddress(&p, g_xh);  __half* xh  = (__half*)p;
    cudaGetSymbolAddress(&p, g_aoh); __half* aoh = (__half*)p;
    cudaGetSymbolAddress(&p, g_wqh); __half* wqh = (__half*)p;
    cudaGetSymbolAddress(&p, g_wph); __half* wph = (__half*)p;

    // converts (graph-capturable, elementwise)
    cvt_half_kernel<<<((MROWS * CD / 4) + 255) / 256, 256>>>(x, xh, MROWS * CD / 4);
    cvt_half_kernel<<<((QKVN * CD / 4) + 255) / 256, 256>>>(qkv_w, wqh, QKVN * CD / 4);
    cvt_half_kernel<<<((CD * CD / 4) + 255) / 256, 256>>>(proj_w, wph, CD * CD / 4);

    cpb_mlp_kernel<<<TBL, 128>>>(cpb_w1, cpb_b1, cpb_w2);
    bias_expand_kernel<<<(NH * NT * NT + 255) / 256, 256>>>();

    dim3 gq(QKVN / 128, MROWS / 128);
    gemm_fp16cp<QKVN, 0><<<gq, 256>>>(xh, wqh, qkv, q_bias, v_bias);

    attn_mma<<<BQ * NH, 128>>>(logit_scale);

    dim3 gp(CD / 128, MROWS / 128);
    gemm_fp16cp<CD, 1><<<gp, 256>>>(aoh, wph, out, proj_b, nullptr);
}

// round 16
// speedup vs baseline: 1.3555x; 1.0225x over previous
#include <cuda_runtime.h>
#include <cuda_fp16.h>
#include <math.h>
#include <cstdint>
#include <cstddef>

#define BQ 2048
#define NT 49
#define CD 384
#define NH 12
#define HD 32
#define MROWS (BQ*NT)        // 100352
#define QKVN (3*CD)          // 1152
#define RPE 512
#define TBL 169
#define LOG_MAX_SCALE 4.60517018598809136804f

__device__ float  g_qkv[(size_t)MROWS * QKVN];
__device__ __half g_xh[(size_t)MROWS * CD];
__device__ __half g_aoh[(size_t)MROWS * CD];
__device__ __half g_wqh[QKVN * CD];
__device__ __half g_wph[CD * CD];
__device__ float  g_tab[TBL * NH];
__device__ float  g_bias[NH * NT * NT];

// ---------------------------------------------------------------------------
// CPB MLP: warp-parallel heads (3 heads per warp, shfl-only reductions)
// ---------------------------------------------------------------------------
__global__ void cpb_mlp_kernel(const float* __restrict__ w1,
                               const float* __restrict__ b1,
                               const float* __restrict__ w2)
{
    int i2 = blockIdx.x;
    int a = i2 / 13, bcol = i2 % 13;
    float vy = (float)(a - 6) * (8.0f / 6.0f);
    float vx = (float)(bcol - 6) * (8.0f / 6.0f);
    float t0 = copysignf(log2f(fabsf(vy) + 1.0f) / 3.0f, vy);
    float t1 = copysignf(log2f(fabsf(vx) + 1.0f) / 3.0f, vx);

    __shared__ float hidden[RPE];
    int tid = threadIdx.x, lane = tid & 31, warp = tid >> 5;
    for (int r = tid; r < RPE; r += 128) {
        float hv = t0 * w1[2 * r] + t1 * w1[2 * r + 1] + b1[r];
        hidden[r] = fmaxf(hv, 0.0f);
    }
    __syncthreads();
    for (int h = warp; h < NH; h += 4) {
        float p = 0.0f;
        for (int r = lane; r < RPE; r += 32) p += hidden[r] * w2[h * RPE + r];
        #pragma unroll
        for (int o = 16; o > 0; o >>= 1) p += __shfl_xor_sync(0xffffffffu, p, o);
        if (lane == 0) g_tab[i2 * NH + h] = p;
    }
}

__global__ void bias_expand_kernel()
{
    int t = blockIdx.x * 256 + threadIdx.x;
    if (t >= NH * NT * NT) return;
    int h = t / (NT * NT);
    int ij = t % (NT * NT);
    int i = ij / NT, j = ij % NT;
    int rel = ((i / 7 - j / 7) + 6) * 13 + ((i % 7 - j % 7) + 6);
    float x = g_tab[rel * NH + h];
    g_bias[t] = 16.0f / (1.0f + __expf(-x));
}

// ---------------------------------------------------------------------------
// common helpers
// ---------------------------------------------------------------------------
__device__ __forceinline__ uint32_t smem_u32(const void* p) {
    uint32_t a;
    asm("{ .reg .u64 t; cvta.to.shared.u64 t, %1; cvt.u32.u64 %0, t; }"
        : "=r"(a) : "l"(p));
    return a;
}

__device__ __forceinline__ uint2 pack4h(float4 v) {
    __half2 h0 = __floats2half2_rn(v.x, v.y);
    __half2 h1 = __floats2half2_rn(v.z, v.w);
    uint2 r;
    r.x = *(uint32_t*)&h0;
    r.y = *(uint32_t*)&h1;
    return r;
}

#define LDSM4(r0, r1, r2, r3, a) \
    asm volatile("ldmatrix.sync.aligned.m8n8.x4.shared.b16 {%0,%1,%2,%3}, [%4];" \
                 : "=r"(r0), "=r"(r1), "=r"(r2), "=r"(r3) : "r"(a))

__device__ __forceinline__ void mma_fp16(float c[4], uint32_t a0, uint32_t a1,
                                         uint32_t a2, uint32_t a3,
                                         uint32_t b0, uint32_t b1) {
    asm volatile(
        "mma.sync.aligned.m16n8k16.row.col.f32.f16.f16.f32 "
        "{%0,%1,%2,%3}, {%4,%5,%6,%7}, {%8,%9}, {%0,%1,%2,%3};"
        : "+f"(c[0]), "+f"(c[1]), "+f"(c[2]), "+f"(c[3])
        : "r"(a0), "r"(a1), "r"(a2), "r"(a3), "r"(b0), "r"(b1));
}

__device__ __forceinline__ void pack_hl(float f0, float f1, uint32_t& hi, uint32_t& lo) {
    __half h0 = __float2half_rn(f0), h1 = __float2half_rn(f1);
    __half l0 = __float2half_rn(f0 - __half2float(h0));
    __half l1 = __float2half_rn(f1 - __half2float(h1));
    hi = (uint32_t)(*(uint16_t*)&h0) | ((uint32_t)(*(uint16_t*)&h1) << 16);
    lo = (uint32_t)(*(uint16_t*)&l0) | ((uint32_t)(*(uint16_t*)&l1) << 16);
}

__device__ __forceinline__ void split_store(uint16_t* hi_p, uint16_t* lo_p, float f) {
    __half h = __float2half_rn(f);
    __half l = __float2half_rn(f - __half2float(h));
    *hi_p = *(uint16_t*)&h;
    *lo_p = *(uint16_t*)&l;
}

#define CP16(dst, src) \
    asm volatile("cp.async.cg.shared.global [%0], [%1], 16;" :: "r"(dst), "l"(src))
#define CP_COMMIT() asm volatile("cp.async.commit_group;" ::: "memory")
#define CP_WAIT(n)  asm volatile("cp.async.wait_group %0;" :: "n"(n) : "memory")

// ---------------------------------------------------------------------------
// fused fp32 -> fp16 convert: x, qkv_w, proj_w in one launch
// ---------------------------------------------------------------------------
#define CVT_N1 (MROWS * CD / 4)
#define CVT_N2 (QKVN * CD / 4)
#define CVT_N3 (CD * CD / 4)

__global__ void cvt_all_kernel(const float* __restrict__ x,
                               const float* __restrict__ wq,
                               const float* __restrict__ wp,
                               __half* __restrict__ xh,
                               __half* __restrict__ wqh,
                               __half* __restrict__ wph)
{
    int i = blockIdx.x * 256 + threadIdx.x;
    if (i < CVT_N1) {
        ((uint2*)xh)[i] = pack4h(((const float4*)x)[i]);
    } else if (i < CVT_N1 + CVT_N2) {
        int j = i - CVT_N1;
        ((uint2*)wqh)[j] = pack4h(((const float4*)wq)[j]);
    } else if (i < CVT_N1 + CVT_N2 + CVT_N3) {
        int j = i - CVT_N1 - CVT_N2;
        ((uint2*)wph)[j] = pack4h(((const float4*)wp)[j]);
    }
}

// ---------------------------------------------------------------------------
// FP16 tensor-core GEMM with cp.async staging (unchanged from round 15)
// ---------------------------------------------------------------------------
#define HROW 40
#define BUFB (128 * HROW * 2)

template<int NC, int MODE>
__global__ void __launch_bounds__(256) gemm_fp16cp(
    const __half* __restrict__ A, const __half* __restrict__ B,
    float* __restrict__ C,
    const float* __restrict__ bias0, const float* __restrict__ bias1)
{
    constexpr int K = 384;
    constexpr int NSTAGE = 12;
    __shared__ __align__(16) uint16_t As[2][128 * HROW];
    __shared__ __align__(16) uint16_t Bs[2][128 * HROW];

    int tid = threadIdx.x;
    int lane = tid & 31, w = tid >> 5;
    int g = lane >> 2, t4 = lane & 3;
    int warp_m = (w >> 1) * 32;
    int warp_n = (w & 1) * 64;
    int m0 = blockIdx.y * 128;
    int n0 = blockIdx.x * 128;

    uint32_t as_u = smem_u32(As), bs_u = smem_u32(Bs);
    int arow = warp_m + ((lane >> 3) & 1) * 8 + (lane & 7);
    uint32_t aaddr = as_u + arow * 80 + (lane >> 4) * 16;
    int brow = warp_n + ((lane >> 4) & 1) * 8 + (lane & 7);
    uint32_t baddr = bs_u + brow * 80 + ((lane >> 3) & 1) * 16;

    int crow = tid >> 2, cseg = tid & 3;
    const __half* Asrc = A + (size_t)(m0 + crow) * K + cseg * 8;
    const __half* Bsrc = B + (size_t)(n0 + crow) * K + cseg * 8;
    uint32_t adst = as_u + crow * 80 + cseg * 16;
    uint32_t bdst = bs_u + crow * 80 + cseg * 16;

    float acc[2][8][4];
    #pragma unroll
    for (int mi = 0; mi < 2; mi++)
        #pragma unroll
        for (int ni = 0; ni < 8; ni++)
            #pragma unroll
            for (int q = 0; q < 4; q++) acc[mi][ni][q] = 0.0f;

    #pragma unroll
    for (int s0 = 0; s0 < 2; s0++) {
        CP16(adst + s0 * BUFB, Asrc + s0 * 32);
        CP16(adst + s0 * BUFB + 64 * 80, Asrc + (size_t)64 * K + s0 * 32);
        CP16(bdst + s0 * BUFB, Bsrc + s0 * 32);
        CP16(bdst + s0 * BUFB + 64 * 80, Bsrc + (size_t)64 * K + s0 * 32);
        CP_COMMIT();
    }

    for (int s = 0; s < NSTAGE; s++) {
        if (s < NSTAGE - 1) { CP_WAIT(1); } else { CP_WAIT(0); }
        __syncthreads();

        int buf = s & 1;
        uint32_t ab = aaddr + buf * BUFB;
        uint32_t bb = baddr + buf * BUFB;
        #pragma unroll
        for (int kk = 0; kk < 2; kk++) {
            uint32_t kb = kk * 32;
            uint32_t af[2][4], bq[4][4];
            #pragma unroll
            for (int mi = 0; mi < 2; mi++)
                LDSM4(af[mi][0], af[mi][1], af[mi][2], af[mi][3],
                      ab + mi * 1280 + kb);
            #pragma unroll
            for (int p = 0; p < 4; p++)
                LDSM4(bq[p][0], bq[p][1], bq[p][2], bq[p][3],
                      bb + p * 1280 + kb);
            #pragma unroll
            for (int mi = 0; mi < 2; mi++)
                #pragma unroll
                for (int ni = 0; ni < 8; ni++) {
                    int p = ni >> 1, hsel = (ni & 1) * 2;
                    mma_fp16(acc[mi][ni], af[mi][0], af[mi][1], af[mi][2], af[mi][3],
                             bq[p][hsel], bq[p][hsel + 1]);
                }
        }
        __syncthreads();

        if (s + 2 < NSTAGE) {
            int nb = s & 1;
            const __half* As2 = Asrc + (s + 2) * 32;
            const __half* Bs2 = Bsrc + (s + 2) * 32;
            CP16(adst + nb * BUFB, As2);
            CP16(adst + nb * BUFB + 64 * 80, As2 + (size_t)64 * K);
            CP16(bdst + nb * BUFB, Bs2);
            CP16(bdst + nb * BUFB + 64 * 80, Bs2 + (size_t)64 * K);
            CP_COMMIT();
        }
    }

    #pragma unroll
    for (int ni = 0; ni < 8; ni++) {
        int col = n0 + warp_n + ni * 8 + 2 * t4;
        float bx, by;
        if (MODE == 0) {
            bx = (col < CD) ? bias0[col] : ((col < 2 * CD) ? 0.0f : bias1[col - 2 * CD]);
            int c1 = col + 1;
            by = (c1 < CD) ? bias0[c1] : ((c1 < 2 * CD) ? 0.0f : bias1[c1 - 2 * CD]);
        } else {
            bx = bias0[col]; by = bias0[col + 1];
        }
        #pragma unroll
        for (int mi = 0; mi < 2; mi++) {
            int row = m0 + warp_m + mi * 16 + g;
            float2 o0 = make_float2(acc[mi][ni][0] + bx, acc[mi][ni][1] + by);
            float2 o1 = make_float2(acc[mi][ni][2] + bx, acc[mi][ni][3] + by);
            *(float2*)(C + (size_t)row * NC + col) = o0;
            *(float2*)(C + (size_t)(row + 8) * NC + col) = o1;
        }
    }
}

// ---------------------------------------------------------------------------
// MMA attention v4: V prefetched via cp.async into smem staging at kernel
// entry (overlaps QK phase); transform reads LDS instead of LDG.
// ---------------------------------------------------------------------------
#define AQ_STR 40
#define AV_STR 72
#define QK_BUF (64 * AQ_STR)
#define QK_BUFB (QK_BUF * 2)
#define VT_BUF (32 * AV_STR)
#define VT_BUFB (VT_BUF * 2)
#define VS_STR 36                  // floats per staging row (32 + 4 pad)

__global__ void __launch_bounds__(128) attn_mma(const float* __restrict__ logit_scale)
{
    __shared__ __align__(16) uint16_t qs[2][QK_BUF];   // reused as V^T after QK
    __shared__ __align__(16) uint16_t ks[2][QK_BUF];
    __shared__ __align__(16) float vstage[NT * VS_STR];

    int bh = blockIdx.x;
    int b = bh / NH, h = bh % NH;
    int tid = threadIdx.x, lane = tid & 31, warp = tid >> 5;
    int g = lane >> 2, t4 = lane & 3;
    float scale = __expf(fminf(logit_scale[h], LOG_MAX_SCALE));

    // ---- issue V cp.async early (completes under the QK phase)
    uint32_t vs_u = smem_u32(vstage);
    for (int u = tid; u < NT * 8; u += 128) {
        int i = u >> 3, s = u & 7;
        const float* src = g_qkv + (size_t)(b * NT + i) * QKVN
                         + (size_t)h * HD + 2 * CD + s * 4;
        CP16(vs_u + i * (VS_STR * 4) + s * 16, src);
    }
    CP_COMMIT();

    // ---- prologue: 8 threads per row, float4 loads, packed split stores
    int rip = tid >> 3;
    int octl = tid & 7;
    #pragma unroll
    for (int p = 0; p < 4; p++) {
        int i = p * 16 + rip;
        int ic = (i < NT) ? i : NT - 1;
        size_t off = (size_t)(b * NT + ic) * QKVN + (size_t)h * HD + octl * 4;
        float4 q4 = *(const float4*)(g_qkv + off);
        float4 k4 = *(const float4*)(g_qkv + off + CD);
        float sq = q4.x * q4.x + q4.y * q4.y + q4.z * q4.z + q4.w * q4.w;
        float sk = k4.x * k4.x + k4.y * k4.y + k4.z * k4.z + k4.w * k4.w;
        #pragma unroll
        for (int o = 1; o < 8; o <<= 1) {
            sq += __shfl_xor_sync(0xffffffffu, sq, o);
            sk += __shfl_xor_sync(0xffffffffu, sk, o);
        }
        if (i < NT) {
            float qsc = scale / (sqrtf(sq) + 1e-12f);
            float ksc = 1.0f / (sqrtf(sk) + 1e-12f);
            int bidx = i * AQ_STR + octl * 4;
            uint32_t hi, lo;
            pack_hl(q4.x * qsc, q4.y * qsc, hi, lo);
            *(uint32_t*)&qs[0][bidx] = hi;  *(uint32_t*)&qs[1][bidx] = lo;
            pack_hl(q4.z * qsc, q4.w * qsc, hi, lo);
            *(uint32_t*)&qs[0][bidx + 2] = hi;  *(uint32_t*)&qs[1][bidx + 2] = lo;
            pack_hl(k4.x * ksc, k4.y * ksc, hi, lo);
            *(uint32_t*)&ks[0][bidx] = hi;  *(uint32_t*)&ks[1][bidx] = lo;
            pack_hl(k4.z * ksc, k4.w * ksc, hi, lo);
            *(uint32_t*)&ks[0][bidx + 2] = hi;  *(uint32_t*)&ks[1][bidx + 2] = lo;
        }
    }
    __syncthreads();

    int r0 = warp * 16;
    float acc[8][4];
    #pragma unroll
    for (int nt = 0; nt < 8; nt++)
        #pragma unroll
        for (int q = 0; q < 4; q++) acc[nt][q] = 0.0f;

    uint32_t qaddr = smem_u32(qs) + (r0 + ((lane >> 3) & 1) * 8 + (lane & 7)) * 80
                   + (lane >> 4) * 16;
    uint32_t kaddr = smem_u32(ks) + (((lane >> 4) & 1) * 8 + (lane & 7)) * 80
                   + ((lane >> 3) & 1) * 16;

    #pragma unroll
    for (int ki = 0; ki < 2; ki++) {
        uint32_t ah[4], al[4];
        LDSM4(ah[0], ah[1], ah[2], ah[3], qaddr + ki * 32);
        LDSM4(al[0], al[1], al[2], al[3], qaddr + QK_BUFB + ki * 32);
        #pragma unroll
        for (int ntp = 0; ntp < 4; ntp++) {
            uint32_t bh_[4], bl_[4];
            LDSM4(bh_[0], bh_[1], bh_[2], bh_[3], kaddr + ntp * 16 * 80 + ki * 32);
            LDSM4(bl_[0], bl_[1], bl_[2], bl_[3], kaddr + QK_BUFB + ntp * 16 * 80 + ki * 32);
            #pragma unroll
            for (int sub = 0; sub < 2; sub++) {
                int nt = ntp * 2 + sub;
                uint32_t b0h = bh_[sub * 2], b1h = bh_[sub * 2 + 1];
                uint32_t b0l = bl_[sub * 2], b1l = bl_[sub * 2 + 1];
                mma_fp16(acc[nt], ah[0], ah[1], ah[2], ah[3], b0h, b1h);
                mma_fp16(acc[nt], ah[0], ah[1], ah[2], ah[3], b0l, b1l);
                mma_fp16(acc[nt], al[0], al[1], al[2], al[3], b0h, b1h);
            }
        }
    }
    CP_WAIT(0);        // own V copies done (long since); then barrier orders all
    __syncthreads();   // all warps done reading qs — safe to overlay V^T

    // ---- transform V from smem staging -> split V^T overlay; zero tail
    uint16_t* vt0 = &qs[0][0];
    uint16_t* vt1 = vt0 + VT_BUF;
    #pragma unroll
    for (int p = 0; p < 4; p++) {
        int i = p * 16 + rip;
        if (i < NT) {
            float4 v4 = *(const float4*)(vstage + i * VS_STR + octl * 4);
            int d0 = octl * 4;
            split_store(&vt0[(d0 + 0) * AV_STR + i], &vt1[(d0 + 0) * AV_STR + i], v4.x);
            split_store(&vt0[(d0 + 1) * AV_STR + i], &vt1[(d0 + 1) * AV_STR + i], v4.y);
            split_store(&vt0[(d0 + 2) * AV_STR + i], &vt1[(d0 + 2) * AV_STR + i], v4.z);
            split_store(&vt0[(d0 + 3) * AV_STR + i], &vt1[(d0 + 3) * AV_STR + i], v4.w);
        }
    }
    for (int u = tid; u < 32 * 15; u += 128) {
        int d = u / 15, j = 49 + (u % 15);
        vt0[d * AV_STR + j] = 0;
        vt1[d * AV_STR + j] = 0;
    }

    // ---- bias + mask + softmax
    int rA = r0 + g, rB = rA + 8;
    int rAc = (rA < NT) ? rA : NT - 1;
    int rBc = (rB < NT) ? rB : NT - 1;
    const float* bias_h = g_bias + h * NT * NT;
    float mA = -1e30f, mB = -1e30f;
    #pragma unroll
    for (int nt = 0; nt < 8; nt++) {
        int c0 = nt * 8 + t4 * 2;
        int c0c = (c0 < NT) ? c0 : NT - 1;
        int c1c = (c0 + 1 < NT) ? c0 + 1 : NT - 1;
        float bA0 = __ldg(bias_h + rAc * NT + c0c);
        float bA1 = __ldg(bias_h + rAc * NT + c1c);
        float bB0 = __ldg(bias_h + rBc * NT + c0c);
        float bB1 = __ldg(bias_h + rBc * NT + c1c);
        acc[nt][0] = (c0 < NT) ? acc[nt][0] + bA0 : -1e30f;
        acc[nt][1] = (c0 + 1 < NT) ? acc[nt][1] + bA1 : -1e30f;
        acc[nt][2] = (c0 < NT) ? acc[nt][2] + bB0 : -1e30f;
        acc[nt][3] = (c0 + 1 < NT) ? acc[nt][3] + bB1 : -1e30f;
        mA = fmaxf(mA, fmaxf(acc[nt][0], acc[nt][1]));
        mB = fmaxf(mB, fmaxf(acc[nt][2], acc[nt][3]));
    }
    mA = fmaxf(mA, __shfl_xor_sync(0xffffffffu, mA, 1));
    mA = fmaxf(mA, __shfl_xor_sync(0xffffffffu, mA, 2));
    mB = fmaxf(mB, __shfl_xor_sync(0xffffffffu, mB, 1));
    mB = fmaxf(mB, __shfl_xor_sync(0xffffffffu, mB, 2));

    float sumA = 0.0f, sumB = 0.0f;
    #pragma unroll
    for (int nt = 0; nt < 8; nt++) {
        float p0 = __expf(acc[nt][0] - mA);
        float p1 = __expf(acc[nt][1] - mA);
        float p2 = __expf(acc[nt][2] - mB);
        float p3 = __expf(acc[nt][3] - mB);
        acc[nt][0] = p0; acc[nt][1] = p1; acc[nt][2] = p2; acc[nt][3] = p3;
        sumA += p0 + p1;
        sumB += p2 + p3;
    }
    sumA += __shfl_xor_sync(0xffffffffu, sumA, 1);
    sumA += __shfl_xor_sync(0xffffffffu, sumA, 2);
    sumB += __shfl_xor_sync(0xffffffffu, sumB, 1);
    sumB += __shfl_xor_sync(0xffffffffu, sumB, 2);
    float invA = __fdividef(1.0f, sumA);
    float invB = __fdividef(1.0f, sumB);

    __syncthreads();   // V^T ready

    // ---- PV
    float o[4][4];
    #pragma unroll
    for (int nd = 0; nd < 4; nd++)
        #pragma unroll
        for (int q = 0; q < 4; q++) o[nd][q] = 0.0f;

    uint32_t vaddr = smem_u32(qs) + (((lane >> 4) & 1) * 8 + (lane & 7)) * 144
                   + ((lane >> 3) & 1) * 16;

    #pragma unroll
    for (int js = 0; js < 4; js++) {
        uint32_t ph[4], pl[4];
        pack_hl(acc[2 * js][0],     acc[2 * js][1],     ph[0], pl[0]);
        pack_hl(acc[2 * js][2],     acc[2 * js][3],     ph[1], pl[1]);
        pack_hl(acc[2 * js + 1][0], acc[2 * js + 1][1], ph[2], pl[2]);
        pack_hl(acc[2 * js + 1][2], acc[2 * js + 1][3], ph[3], pl[3]);
        #pragma unroll
        for (int ndp = 0; ndp < 2; ndp++) {
            uint32_t vh_[4], vl_[4];
            LDSM4(vh_[0], vh_[1], vh_[2], vh_[3],
                  vaddr + ndp * 16 * 144 + js * 32);
            LDSM4(vl_[0], vl_[1], vl_[2], vl_[3],
                  vaddr + VT_BUFB + ndp * 16 * 144 + js * 32);
            #pragma unroll
            for (int sub = 0; sub < 2; sub++) {
                int nd = ndp * 2 + sub;
                uint32_t b0h = vh_[sub * 2], b1h = vh_[sub * 2 + 1];
                uint32_t b0l = vl_[sub * 2], b1l = vl_[sub * 2 + 1];
                mma_fp16(o[nd], ph[0], ph[1], ph[2], ph[3], b0h, b1h);
                mma_fp16(o[nd], ph[0], ph[1], ph[2], ph[3], b0l, b1l);
                mma_fp16(o[nd], pl[0], pl[1], pl[2], pl[3], b0h, b1h);
            }
        }
    }

    // ---- store fp16 (half2)
    if (rA < NT) {
        __half* dst = g_aoh + (size_t)(b * NT + rA) * CD + h * HD;
        #pragma unroll
        for (int nd = 0; nd < 4; nd++) {
            int d = nd * 8 + t4 * 2;
            __half2 hv = __floats2half2_rn(o[nd][0] * invA, o[nd][1] * invA);
            *(__half2*)(dst + d) = hv;
        }
    }
    if (rB < NT) {
        __half* dst = g_aoh + (size_t)(b * NT + rB) * CD + h * HD;
        #pragma unroll
        for (int nd = 0; nd < 4; nd++) {
            int d = nd * 8 + t4 * 2;
            __half2 hv = __floats2half2_rn(o[nd][2] * invB, o[nd][3] * invB);
            *(__half2*)(dst + d) = hv;
        }
    }
}

// ---------------------------------------------------------------------------
extern "C" void kernel_launch(void* const* d_in, const int* in_sizes, int n_in,
                              void* d_out, int out_size)
{
    const float* x           = (const float*)d_in[0];
    const float* qkv_w       = (const float*)d_in[1];
    const float* q_bias      = (const float*)d_in[2];
    const float* v_bias      = (const float*)d_in[3];
    const float* logit_scale = (const float*)d_in[4];
    const float* cpb_w1      = (const float*)d_in[5];
    const float* cpb_b1      = (const float*)d_in[6];
    const float* cpb_w2      = (const float*)d_in[7];
    const float* proj_w      = (const float*)d_in[8];
    const float* proj_b      = (const float*)d_in[9];
    float* out = (float*)d_out;

    void* p;
    cudaGetSymbolAddress(&p, g_qkv); float*  qkv = (float*)p;
    cudaGetSymbolAddress(&p, g_xh);  __half* xh  = (__half*)p;
    cudaGetSymbolAddress(&p, g_aoh); __half* aoh = (__half*)p;
    cudaGetSymbolAddress(&p, g_wqh); __half* wqh = (__half*)p;
    cudaGetSymbolAddress(&p, g_wph); __half* wph = (__half*)p;

    int cvt_total = CVT_N1 + CVT_N2 + CVT_N3;
    cvt_all_kernel<<<(cvt_total + 255) / 256, 256>>>(x, qkv_w, proj_w, xh, wqh, wph);

    cpb_mlp_kernel<<<TBL, 128>>>(cpb_w1, cpb_b1, cpb_w2);
    bias_expand_kernel<<<(NH * NT * NT + 255) / 256, 256>>>();

    dim3 gq(QKVN / 128, MROWS / 128);
    gemm_fp16cp<QKVN, 0><<<gq, 256>>>(xh, wqh, qkv, q_bias, v_bias);

    attn_mma<<<BQ * NH, 128>>>(logit_scale);

    dim3 gp(CD / 128, MROWS / 128);
    gemm_fp16cp<CD, 1><<<gp, 256>>>(aoh, wph, out, proj_b, nullptr);
}